// round 7
// baseline (speedup 1.0000x reference)
#include <cuda_runtime.h>

// Plenoxel forward: R=4096 rays, S=128 samples/ray, 160^3 grid.
// d_in[0] ray_origins float32[R,3], d_in[1] ray_directions float32[R,3],
// d_in[2] density float32[160^3], d_in[3] sh_coeffs float32[160^3,3,9]
// out: concat(rgb[R,3], depth[R], acc[R])

#define GRES        160
#define NSAMP       128
#define T_NEAR      0.1f
#define T_FAR       10.0f
#define FULLMASK    0xffffffffu

// Build shifted basis: bs[k] = b[k-O] for 0<=k-O<9 else 0 (O = F&3).
__device__ __forceinline__ void build_bs(const float (&b)[9], int O, float (&bs)[12])
{
    const bool s2 = (O & 2) != 0;
    const bool s1 = (O & 1) != 0;
    float t[12];
    t[0]  = s2 ? 0.f  : b[0];
    t[1]  = s2 ? 0.f  : b[1];
    #pragma unroll
    for (int k = 2; k <= 8; k++) t[k] = s2 ? b[k-2] : b[k];
    t[9]  = s2 ? b[7] : 0.f;
    t[10] = s2 ? b[8] : 0.f;
    t[11] = 0.f;
    bs[0] = s1 ? 0.f : t[0];
    #pragma unroll
    for (int k = 1; k < 12; k++) bs[k] = s1 ? t[k-1] : t[k];
}

// Fused x-pair: accumulate w0*(row(idx0).b) + w1*(row(idx1).b) into 3 channels.
// ALL loads of both rows are issued as one batch (MLP ~16); when xd=1 the two
// windows share L1 lines (rows are adjacent in memory), cutting wavefronts.
__device__ __forceinline__ void sh_pair_accum(const float4* __restrict__ sh4,
                                              int idx0, int idx1,
                                              const float (&b)[9],
                                              float w0, float w1,
                                              float& c0, float& c1, float& c2)
{
    const int F0 = idx0 * 27, base0 = F0 >> 2, O0 = F0 & 3;
    const int F1 = idx1 * 27, base1 = F1 >> 2, O1 = F1 & 3;
    const bool s2_0 = (O0 & 2) != 0;
    const bool s2_1 = (O1 & 2) != 0;

    // ---- batched loads: both rows' windows ----
    float v0[32], v1[32];
    #pragma unroll
    for (int i = 0; i < 7; i++) {
        const float4 q = __ldg(sh4 + base0 + i);
        v0[4*i+0] = q.x; v0[4*i+1] = q.y; v0[4*i+2] = q.z; v0[4*i+3] = q.w;
    }
    #pragma unroll
    for (int i = 0; i < 7; i++) {
        const float4 q = __ldg(sh4 + base1 + i);
        v1[4*i+0] = q.x; v1[4*i+1] = q.y; v1[4*i+2] = q.z; v1[4*i+3] = q.w;
    }
    {   // conditional 8th chunks (needed & in-bounds only when O>=2)
        float4 q = make_float4(0.f, 0.f, 0.f, 0.f);
        if (s2_0) q = __ldg(sh4 + base0 + 7);
        v0[28] = q.x; v0[29] = q.y; v0[30] = q.z; v0[31] = q.w;
    }
    {
        float4 q = make_float4(0.f, 0.f, 0.f, 0.f);
        if (s2_1) q = __ldg(sh4 + base1 + 7);
        v1[28] = q.x; v1[29] = q.y; v1[30] = q.z; v1[31] = q.w;
    }

    // ---- shifted bases (independent of loads; fills load latency) ----
    float bs0[12], bs1[12];
    build_bs(b, O0, bs0);
    build_bs(b, O1, bs1);

    // ---- dots ----
    float a0 = 0.f, a1 = 0.f, a2 = 0.f;
    float e0 = 0.f, e1 = 0.f, e2 = 0.f;
    #pragma unroll
    for (int k = 0; k < 12; k++) {
        const float bk0 = bs0[k];
        a0 = fmaf(v0[k],      bk0, a0);
        a1 = fmaf(v0[9 + k],  bk0, a1);
        a2 = fmaf(v0[18 + k], bk0, a2);
        const float bk1 = bs1[k];
        e0 = fmaf(v1[k],      bk1, e0);
        e1 = fmaf(v1[9 + k],  bk1, e1);
        e2 = fmaf(v1[18 + k], bk1, e2);
    }
    c0 = fmaf(w0, a0, c0); c0 = fmaf(w1, e0, c0);
    c1 = fmaf(w0, a1, c1); c1 = fmaf(w1, e1, c1);
    c2 = fmaf(w0, a2, c2); c2 = fmaf(w1, e2, c2);
}

__global__ __launch_bounds__(128, 4) void plenoxel_fwd_kernel(
    const float* __restrict__ ro,
    const float* __restrict__ rd,
    const float* __restrict__ density,
    const float* __restrict__ sh,
    float* __restrict__ out,
    int R)
{
    const float4* __restrict__ sh4 = (const float4*)sh;

    const int wir  = threadIdx.x >> 5;      // warp-in-ray 0..3
    const int lane = threadIdx.x & 31;
    const int r    = blockIdx.x;             // 1 ray per 128-thread block

    __shared__ float sProd[4];
    __shared__ float sPart[4][5];

    const float ox = ro[r*3+0], oy = ro[r*3+1], oz = ro[r*3+2];
    const float dx = rd[r*3+0], dy = rd[r*3+1], dz = rd[r*3+2];

    const float dnorm = sqrtf(dx*dx + dy*dy + dz*dz);
    const float inv   = 1.0f / (dnorm + 1e-8f);
    const float nx = dx*inv, ny = dy*inv, nz = dz*inv;

    float b[9];
    b[0] =  0.28209479177387814f;
    b[1] = -0.48860251190291987f * ny;
    b[2] =  0.48860251190291987f * nz;
    b[3] = -0.48860251190291987f * nx;
    b[4] =  1.0925484305920792f  * nx * ny;
    b[5] = -1.0925484305920792f  * ny * nz;
    b[6] =  0.31539156525252005f * (2.0f*nz*nz - nx*nx - ny*ny);
    b[7] = -1.0925484305920792f  * nx * nz;
    b[8] =  0.5462742152960396f  * (nx*nx - ny*ny);

    const float dt = (T_FAR - T_NEAR) / (float)(NSAMP - 1);

    // --- one sample per lane ---
    const int   s = wir * 32 + lane;
    const float t = T_NEAR + dt * (float)s;

    float vx = (ox + t*dx + 1.0f) * 80.0f;
    float vy = (oy + t*dy + 1.0f) * 80.0f;
    float vz = (oz + t*dz + 1.0f) * 80.0f;
    vx = fminf(fmaxf(vx, 0.0f), 159.0f);
    vy = fminf(fmaxf(vy, 0.0f), 159.0f);
    vz = fminf(fmaxf(vz, 0.0f), 159.0f);

    const float fx = floorf(vx), fy = floorf(vy), fz = floorf(vz);
    const int x0 = (int)fx, y0 = (int)fy, z0 = (int)fz;
    const int x1 = min(x0 + 1, GRES - 1);
    const int y1 = min(y0 + 1, GRES - 1);
    const int z1 = min(z0 + 1, GRES - 1);
    const float ddx = vx - fx, ddy = vy - fy, ddz = vz - fz;
    const float wx0 = 1.0f - ddx, wx1 = ddx;
    const int   xd  = x1 - x0;

    // ---- Phase 1: density (cheap), alpha, warp transmittance scan ----
    float dens = 0.0f;
    {
        const int  rz0 = z0 * GRES, rz1 = z1 * GRES;
        const int  i00 = (rz0 + y0) * GRES + x0;
        const int  i01 = (rz0 + y1) * GRES + x0;
        const int  i10 = (rz1 + y0) * GRES + x0;
        const int  i11 = (rz1 + y1) * GRES + x0;
        const float wz0 = 1.0f - ddz, wz1 = ddz;
        const float wy0 = 1.0f - ddy, wy1 = ddy;

        const float d000 = __ldg(density + i00),  d001 = __ldg(density + i00 + xd);
        const float d010 = __ldg(density + i01),  d011 = __ldg(density + i01 + xd);
        const float d100 = __ldg(density + i10),  d101 = __ldg(density + i10 + xd);
        const float d110 = __ldg(density + i11),  d111 = __ldg(density + i11 + xd);

        dens = wz0 * (wy0 * (wx0*d000 + wx1*d001) + wy1 * (wx0*d010 + wx1*d011))
             + wz1 * (wy0 * (wx0*d100 + wx1*d101) + wy1 * (wx0*d110 + wx1*d111));
    }

    const float dist  = ((s == NSAMP - 1) ? 1e10f : dt) * dnorm;
    const float alpha = 1.0f - __expf(-fmaxf(dens, 0.0f) * dist);

    float incl = 1.0f - alpha + 1e-10f;
    #pragma unroll
    for (int o = 1; o < 32; o <<= 1) {
        const float pv = __shfl_up_sync(FULLMASK, incl, o);
        if (lane >= o) incl *= pv;
    }
    float excl = __shfl_up_sync(FULLMASK, incl, 1);
    if (lane == 0) excl = 1.0f;
    const float warpProd = __shfl_sync(FULLMASK, incl, 31);

    const float w = alpha * excl;   // warp-local weight

    // ---- Phase 2: SH gather + shade, only for nonzero-weight lanes ----
    float col0 = 0.f, col1 = 0.f, col2 = 0.f;
    if (w != 0.0f) {
        float c0 = 0.0f, c1 = 0.0f, c2 = 0.0f;
        #pragma unroll 1
        for (int cz = 0; cz < 2; cz++) {
            const int   zi = cz ? z1 : z0;
            const float wz = cz ? ddz : (1.0f - ddz);
            #pragma unroll 1
            for (int cy = 0; cy < 2; cy++) {
                const int   yi  = cy ? y1 : y0;
                const float wy  = cy ? ddy : (1.0f - ddy);
                const float wyz = wz * wy;
                const int idx0 = (zi * GRES + yi) * GRES + x0;

                sh_pair_accum(sh4, idx0, idx0 + xd, b,
                              wyz * wx0, wyz * wx1, c0, c1, c2);
            }
        }
        col0 = __fdividef(1.0f, 1.0f + __expf(-c0));
        col1 = __fdividef(1.0f, 1.0f + __expf(-c1));
        col2 = __fdividef(1.0f, 1.0f + __expf(-c2));
    }

    float rgb0 = w * col0;
    float rgb1 = w * col1;
    float rgb2 = w * col2;
    float dep  = w * t;
    float acc  = w;

    #pragma unroll
    for (int o = 16; o > 0; o >>= 1) {
        rgb0 += __shfl_xor_sync(FULLMASK, rgb0, o);
        rgb1 += __shfl_xor_sync(FULLMASK, rgb1, o);
        rgb2 += __shfl_xor_sync(FULLMASK, rgb2, o);
        dep  += __shfl_xor_sync(FULLMASK, dep,  o);
        acc  += __shfl_xor_sync(FULLMASK, acc,  o);
    }

    if (lane == 0) {
        sPart[wir][0] = rgb0;
        sPart[wir][1] = rgb1;
        sPart[wir][2] = rgb2;
        sPart[wir][3] = dep;
        sPart[wir][4] = acc;
        sProd[wir]    = warpProd;
    }
    __syncthreads();

    if (threadIdx.x == 0) {
        float P = 1.0f;
        float o0 = 0.f, o1 = 0.f, o2 = 0.f, od = 0.f, oa = 0.f;
        #pragma unroll
        for (int ws = 0; ws < 4; ws++) {
            o0 += P * sPart[ws][0];
            o1 += P * sPart[ws][1];
            o2 += P * sPart[ws][2];
            od += P * sPart[ws][3];
            oa += P * sPart[ws][4];
            P  *= sProd[ws];
        }
        out[r*3 + 0] = o0;
        out[r*3 + 1] = o1;
        out[r*3 + 2] = o2;
        out[R*3 + r] = od;
        out[R*4 + r] = oa;
    }
}

extern "C" void kernel_launch(void* const* d_in, const int* in_sizes, int n_in,
                              void* d_out, int out_size)
{
    const float* ro      = (const float*)d_in[0];
    const float* rd      = (const float*)d_in[1];
    const float* density = (const float*)d_in[2];
    const float* sh      = (const float*)d_in[3];
    float* out           = (float*)d_out;

    const int R = in_sizes[0] / 3;      // 4096
    plenoxel_fwd_kernel<<<R, 128>>>(ro, rd, density, sh, out, R);
}

// round 8
// speedup vs baseline: 1.0872x; 1.0872x over previous
#include <cuda_runtime.h>

// Plenoxel forward: R=4096 rays, S=128 samples/ray, 160^3 grid.
// d_in[0] ray_origins float32[R,3], d_in[1] ray_directions float32[R,3],
// d_in[2] density float32[160^3], d_in[3] sh_coeffs float32[160^3,3,9]
// out: concat(rgb[R,3], depth[R], acc[R])
//
// Block = 128 threads = 1 ray (1 sample/lane).
// Phase 1: density interp, alpha, GLOBAL transmittance weight w per sample.
// Dedup:   runs of identical clamped coords (frozen ray tails) fold their
//          weights into one representative (colors are bit-identical).
// Compact: surviving (sample,w) pairs -> smem list; dense worker warps do the
//          expensive SH gather with 100% active lanes.

#define GRES        160
#define NSAMP       128
#define T_NEAR      0.1f
#define T_FAR       10.0f
#define FULLMASK    0xffffffffu

// R6-style: batched 8-chunk window (max MLP) + shifted-basis (23 SELs).
__device__ __forceinline__ void sh_row_accum(const float4* __restrict__ sh4, int idx,
                                             const float (&b)[9], float wgt,
                                             float& c0, float& c1, float& c2)
{
    const int F    = idx * 27;
    const int base = F >> 2;
    const int O    = F & 3;
    const bool s2  = (O & 2) != 0;
    const bool s1  = (O & 1) != 0;

    float v[32];
    #pragma unroll
    for (int i = 0; i < 7; i++) {
        const float4 q = __ldg(sh4 + base + i);
        v[4*i+0] = q.x; v[4*i+1] = q.y; v[4*i+2] = q.z; v[4*i+3] = q.w;
    }
    {   // 8th chunk only needed (and only in-bounds-required) when O>=2
        float4 q = make_float4(0.f, 0.f, 0.f, 0.f);
        if (s2) q = __ldg(sh4 + base + 7);
        v[28] = q.x; v[29] = q.y; v[30] = q.z; v[31] = q.w;
    }

    float t[12];
    t[0]  = s2 ? 0.f  : b[0];
    t[1]  = s2 ? 0.f  : b[1];
    #pragma unroll
    for (int k = 2; k <= 8; k++) t[k] = s2 ? b[k-2] : b[k];
    t[9]  = s2 ? b[7] : 0.f;
    t[10] = s2 ? b[8] : 0.f;
    t[11] = 0.f;

    float bs[12];
    bs[0] = s1 ? 0.f : t[0];
    #pragma unroll
    for (int k = 1; k < 12; k++) bs[k] = s1 ? t[k-1] : t[k];

    float d0 = 0.f, d1 = 0.f, d2 = 0.f;
    #pragma unroll
    for (int k = 0; k < 12; k++) {
        const float bk = bs[k];
        d0 = fmaf(v[k],      bk, d0);
        d1 = fmaf(v[9 + k],  bk, d1);
        d2 = fmaf(v[18 + k], bk, d2);
    }
    c0 = fmaf(wgt, d0, c0);
    c1 = fmaf(wgt, d1, c1);
    c2 = fmaf(wgt, d2, c2);
}

__global__ __launch_bounds__(128) void plenoxel_fwd_kernel(
    const float* __restrict__ ro,
    const float* __restrict__ rd,
    const float* __restrict__ density,
    const float* __restrict__ sh,
    float* __restrict__ out,
    int R)
{
    const float4* __restrict__ sh4 = (const float4*)sh;

    const int wir  = threadIdx.x >> 5;      // warp 0..3
    const int lane = threadIdx.x & 31;
    const int r    = blockIdx.x;             // one ray per block
    const int s    = threadIdx.x;             // sample 0..127 (consecutive in lanes)

    __shared__ float         sProd[4];
    __shared__ float         sDep[4], sAcc[4];
    __shared__ float         sWacc[4][3];
    __shared__ unsigned char sSid[128];
    __shared__ float         sW[128];
    __shared__ int           sWarpCnt[4];

    const float ox = ro[r*3+0], oy = ro[r*3+1], oz = ro[r*3+2];
    const float dx = rd[r*3+0], dy = rd[r*3+1], dz = rd[r*3+2];

    const float dnorm = sqrtf(dx*dx + dy*dy + dz*dz);
    const float inv   = 1.0f / (dnorm + 1e-8f);
    const float nx = dx*inv, ny = dy*inv, nz = dz*inv;

    float b[9];
    b[0] =  0.28209479177387814f;
    b[1] = -0.48860251190291987f * ny;
    b[2] =  0.48860251190291987f * nz;
    b[3] = -0.48860251190291987f * nx;
    b[4] =  1.0925484305920792f  * nx * ny;
    b[5] = -1.0925484305920792f  * ny * nz;
    b[6] =  0.31539156525252005f * (2.0f*nz*nz - nx*nx - ny*ny);
    b[7] = -1.0925484305920792f  * nx * nz;
    b[8] =  0.5462742152960396f  * (nx*nx - ny*ny);

    const float dt = (T_FAR - T_NEAR) / (float)(NSAMP - 1);
    const float t  = T_NEAR + dt * (float)s;

    float vx = (ox + t*dx + 1.0f) * 80.0f;
    float vy = (oy + t*dy + 1.0f) * 80.0f;
    float vz = (oz + t*dz + 1.0f) * 80.0f;
    vx = fminf(fmaxf(vx, 0.0f), 159.0f);
    vy = fminf(fmaxf(vy, 0.0f), 159.0f);
    vz = fminf(fmaxf(vz, 0.0f), 159.0f);

    const float fx = floorf(vx), fy = floorf(vy), fz = floorf(vz);
    const int x0 = (int)fx, y0 = (int)fy, z0 = (int)fz;
    const int x1 = min(x0 + 1, GRES - 1);
    const int y1 = min(y0 + 1, GRES - 1);
    const int z1 = min(z0 + 1, GRES - 1);
    const float ddx = vx - fx, ddy = vy - fy, ddz = vz - fz;
    const float wx0 = 1.0f - ddx, wx1 = ddx;
    const int   xd  = x1 - x0;

    // ---- Phase 1: density interp + alpha ----
    float dens;
    {
        const int  rz0 = z0 * GRES, rz1 = z1 * GRES;
        const int  i00 = (rz0 + y0) * GRES + x0;
        const int  i01 = (rz0 + y1) * GRES + x0;
        const int  i10 = (rz1 + y0) * GRES + x0;
        const int  i11 = (rz1 + y1) * GRES + x0;
        const float wz0 = 1.0f - ddz, wz1 = ddz;
        const float wy0 = 1.0f - ddy, wy1 = ddy;

        const float d000 = __ldg(density + i00),  d001 = __ldg(density + i00 + xd);
        const float d010 = __ldg(density + i01),  d011 = __ldg(density + i01 + xd);
        const float d100 = __ldg(density + i10),  d101 = __ldg(density + i10 + xd);
        const float d110 = __ldg(density + i11),  d111 = __ldg(density + i11 + xd);

        dens = wz0 * (wy0 * (wx0*d000 + wx1*d001) + wy1 * (wx0*d010 + wx1*d011))
             + wz1 * (wy0 * (wx0*d100 + wx1*d101) + wy1 * (wx0*d110 + wx1*d111));
    }

    const float dist  = ((s == NSAMP - 1) ? 1e10f : dt) * dnorm;
    const float alpha = 1.0f - __expf(-fmaxf(dens, 0.0f) * dist);

    // warp-local exclusive cumprod of (1 - alpha + 1e-10)
    float incl = 1.0f - alpha + 1e-10f;
    #pragma unroll
    for (int o = 1; o < 32; o <<= 1) {
        const float pv = __shfl_up_sync(FULLMASK, incl, o);
        if (lane >= o) incl *= pv;
    }
    float excl = __shfl_up_sync(FULLMASK, incl, 1);
    if (lane == 0) excl = 1.0f;
    const float warpProd = __shfl_sync(FULLMASK, incl, 31);

    if (lane == 0) sProd[wir] = warpProd;
    __syncthreads();

    // GLOBAL transmittance: prefix product of earlier warps
    float P = 1.0f;
    #pragma unroll
    for (int j = 0; j < 3; j++) if (j < wir) P *= sProd[j];
    const float w = alpha * excl * P;    // global weight of this sample

    // ---- depth/acc: per-warp fixed-order reduction (uses ALL samples) ----
    {
        float dep = w * t, acc = w;
        #pragma unroll
        for (int o = 16; o > 0; o >>= 1) {
            dep += __shfl_xor_sync(FULLMASK, dep, o);
            acc += __shfl_xor_sync(FULLMASK, acc, o);
        }
        if (lane == 0) { sDep[wir] = dep; sAcc[wir] = acc; }
    }

    // ---- Dedup: fold weights of identical-coord runs (frozen tails) ----
    // Identical clamped (vx,vy,vz) => identical color, so run contributes
    // col * sum(w). Representative = first lane of run within the warp.
    const float pvx = __shfl_up_sync(FULLMASK, vx, 1);
    const float pvy = __shfl_up_sync(FULLMASK, vy, 1);
    const float pvz = __shfl_up_sync(FULLMASK, vz, 1);
    const bool start = (lane == 0) || (vx != pvx) || (vy != pvy) || (vz != pvz);

    const unsigned sb      = __ballot_sync(FULLMASK, start);
    const unsigned mask_le = 0xffffffffu >> (31 - lane);
    const int      segid   = __popc(sb & mask_le);

    float wrun = w;
    #pragma unroll
    for (int o = 1; o < 32; o <<= 1) {
        const float wn = __shfl_down_sync(FULLMASK, wrun, o);
        const int   sn = __shfl_down_sync(FULLMASK, segid, o);
        if (lane + o < 32 && sn == segid) wrun += wn;
    }

    // ---- Compact surviving work items into smem ----
    const bool push = start && (wrun != 0.0f);
    const unsigned pb = __ballot_sync(FULLMASK, push);
    if (lane == 0) sWarpCnt[wir] = __popc(pb);
    __syncthreads();

    int base = 0, cnt = 0;
    #pragma unroll
    for (int j = 0; j < 4; j++) {
        if (j < wir) base += sWarpCnt[j];
        cnt += sWarpCnt[j];
    }
    if (push) {
        const unsigned mask_lt = mask_le ^ (1u << lane);
        const int pos = base + __popc(pb & mask_lt);
        sSid[pos] = (unsigned char)s;
        sW[pos]   = wrun;
    }
    __syncthreads();

    // ---- Worker phase: dense warps over compacted items ----
    float rgb0 = 0.f, rgb1 = 0.f, rgb2 = 0.f;
    if (threadIdx.x < cnt) {
        const int   ss = sSid[threadIdx.x];
        const float ww = sW[threadIdx.x];
        const float tt = T_NEAR + dt * (float)ss;

        float ux = (ox + tt*dx + 1.0f) * 80.0f;
        float uy = (oy + tt*dy + 1.0f) * 80.0f;
        float uz = (oz + tt*dz + 1.0f) * 80.0f;
        ux = fminf(fmaxf(ux, 0.0f), 159.0f);
        uy = fminf(fmaxf(uy, 0.0f), 159.0f);
        uz = fminf(fmaxf(uz, 0.0f), 159.0f);

        const float gx = floorf(ux), gy = floorf(uy), gz = floorf(uz);
        const int a0 = (int)gx, b0i = (int)gy, c0i = (int)gz;
        const int a1 = min(a0 + 1, GRES - 1);
        const int b1i = min(b0i + 1, GRES - 1);
        const int c1i = min(c0i + 1, GRES - 1);
        const float ex = ux - gx, ey = uy - gy, ez = uz - gz;
        const float qx0 = 1.0f - ex, qx1 = ex;
        const int   ad  = a1 - a0;

        float c0 = 0.f, c1 = 0.f, c2 = 0.f;
        #pragma unroll 1
        for (int cz = 0; cz < 2; cz++) {
            const int   zi = cz ? c1i : c0i;
            const float wz = cz ? ez : (1.0f - ez);
            #pragma unroll 1
            for (int cy = 0; cy < 2; cy++) {
                const int   yi  = cy ? b1i : b0i;
                const float wy  = cy ? ey : (1.0f - ey);
                const float wyz = wz * wy;
                const int idx0 = (zi * GRES + yi) * GRES + a0;

                sh_row_accum(sh4, idx0,      b, wyz * qx0, c0, c1, c2);
                sh_row_accum(sh4, idx0 + ad, b, wyz * qx1, c0, c1, c2);
            }
        }
        const float col0 = __fdividef(1.0f, 1.0f + __expf(-c0));
        const float col1 = __fdividef(1.0f, 1.0f + __expf(-c1));
        const float col2 = __fdividef(1.0f, 1.0f + __expf(-c2));
        rgb0 = ww * col0;
        rgb1 = ww * col1;
        rgb2 = ww * col2;
    }

    // fixed-order warp reduction of rgb partials (zeros from idle lanes)
    #pragma unroll
    for (int o = 16; o > 0; o >>= 1) {
        rgb0 += __shfl_xor_sync(FULLMASK, rgb0, o);
        rgb1 += __shfl_xor_sync(FULLMASK, rgb1, o);
        rgb2 += __shfl_xor_sync(FULLMASK, rgb2, o);
    }
    if (lane == 0) {
        sWacc[wir][0] = rgb0;
        sWacc[wir][1] = rgb1;
        sWacc[wir][2] = rgb2;
    }
    __syncthreads();

    if (threadIdx.x == 0) {
        float o0 = 0.f, o1 = 0.f, o2 = 0.f, od = 0.f, oa = 0.f;
        #pragma unroll
        for (int j = 0; j < 4; j++) {
            o0 += sWacc[j][0];
            o1 += sWacc[j][1];
            o2 += sWacc[j][2];
            od += sDep[j];
            oa += sAcc[j];
        }
        out[r*3 + 0] = o0;
        out[r*3 + 1] = o1;
        out[r*3 + 2] = o2;
        out[R*3 + r] = od;
        out[R*4 + r] = oa;
    }
}

extern "C" void kernel_launch(void* const* d_in, const int* in_sizes, int n_in,
                              void* d_out, int out_size)
{
    const float* ro      = (const float*)d_in[0];
    const float* rd      = (const float*)d_in[1];
    const float* density = (const float*)d_in[2];
    const float* sh      = (const float*)d_in[3];
    float* out           = (float*)d_out;

    const int R = in_sizes[0] / 3;      // 4096 rays, 1 ray per 128-thread block
    plenoxel_fwd_kernel<<<R, 128>>>(ro, rd, density, sh, out, R);
}

// round 9
// speedup vs baseline: 1.1464x; 1.0545x over previous
#include <cuda_runtime.h>

// Plenoxel forward: R=4096 rays, S=128 samples/ray, 160^3 grid.
// Block = 128 threads = 1 ray (1 sample/lane in phase 1).
// Phase 1: density interp, alpha, GLOBAL transmittance weight w per sample.
// Dedup:   runs of identical clamped coords fold weights into one rep.
// Compact: surviving (sample,w) -> smem; worker phase assigns 2 LANES PER ITEM
//          (parity = z-plane) to halve the serial chain and double issue density.

#define GRES        160
#define NSAMP       128
#define T_NEAR      0.1f
#define T_FAR       10.0f
#define FULLMASK    0xffffffffu

// Batched 8-chunk window (max MLP) + shifted-basis (23 SELs).
__device__ __forceinline__ void sh_row_accum(const float4* __restrict__ sh4, int idx,
                                             const float (&b)[9], float wgt,
                                             float& c0, float& c1, float& c2)
{
    const int F    = idx * 27;
    const int base = F >> 2;
    const int O    = F & 3;
    const bool s2  = (O & 2) != 0;
    const bool s1  = (O & 1) != 0;

    float v[32];
    #pragma unroll
    for (int i = 0; i < 7; i++) {
        const float4 q = __ldg(sh4 + base + i);
        v[4*i+0] = q.x; v[4*i+1] = q.y; v[4*i+2] = q.z; v[4*i+3] = q.w;
    }
    {   // 8th chunk only needed (and only in-bounds-required) when O>=2
        float4 q = make_float4(0.f, 0.f, 0.f, 0.f);
        if (s2) q = __ldg(sh4 + base + 7);
        v[28] = q.x; v[29] = q.y; v[30] = q.z; v[31] = q.w;
    }

    float t[12];
    t[0]  = s2 ? 0.f  : b[0];
    t[1]  = s2 ? 0.f  : b[1];
    #pragma unroll
    for (int k = 2; k <= 8; k++) t[k] = s2 ? b[k-2] : b[k];
    t[9]  = s2 ? b[7] : 0.f;
    t[10] = s2 ? b[8] : 0.f;
    t[11] = 0.f;

    float bs[12];
    bs[0] = s1 ? 0.f : t[0];
    #pragma unroll
    for (int k = 1; k < 12; k++) bs[k] = s1 ? t[k-1] : t[k];

    float d0 = 0.f, d1 = 0.f, d2 = 0.f;
    #pragma unroll
    for (int k = 0; k < 12; k++) {
        const float bk = bs[k];
        d0 = fmaf(v[k],      bk, d0);
        d1 = fmaf(v[9 + k],  bk, d1);
        d2 = fmaf(v[18 + k], bk, d2);
    }
    c0 = fmaf(wgt, d0, c0);
    c1 = fmaf(wgt, d1, c1);
    c2 = fmaf(wgt, d2, c2);
}

__global__ __launch_bounds__(128) void plenoxel_fwd_kernel(
    const float* __restrict__ ro,
    const float* __restrict__ rd,
    const float* __restrict__ density,
    const float* __restrict__ sh,
    float* __restrict__ out,
    int R)
{
    const float4* __restrict__ sh4 = (const float4*)sh;

    const int wir  = threadIdx.x >> 5;      // warp 0..3
    const int lane = threadIdx.x & 31;
    const int r    = blockIdx.x;             // one ray per block
    const int s    = threadIdx.x;             // sample 0..127

    __shared__ float         sProd[4];
    __shared__ float         sDep[4], sAcc[4];
    __shared__ float         sWacc[4][3];
    __shared__ unsigned char sSid[128];
    __shared__ float         sW[128];
    __shared__ int           sWarpCnt[4];

    const float ox = ro[r*3+0], oy = ro[r*3+1], oz = ro[r*3+2];
    const float dx = rd[r*3+0], dy = rd[r*3+1], dz = rd[r*3+2];

    const float dnorm = sqrtf(dx*dx + dy*dy + dz*dz);
    const float inv   = 1.0f / (dnorm + 1e-8f);
    const float nx = dx*inv, ny = dy*inv, nz = dz*inv;

    float b[9];
    b[0] =  0.28209479177387814f;
    b[1] = -0.48860251190291987f * ny;
    b[2] =  0.48860251190291987f * nz;
    b[3] = -0.48860251190291987f * nx;
    b[4] =  1.0925484305920792f  * nx * ny;
    b[5] = -1.0925484305920792f  * ny * nz;
    b[6] =  0.31539156525252005f * (2.0f*nz*nz - nx*nx - ny*ny);
    b[7] = -1.0925484305920792f  * nx * nz;
    b[8] =  0.5462742152960396f  * (nx*nx - ny*ny);

    const float dt = (T_FAR - T_NEAR) / (float)(NSAMP - 1);
    const float t  = T_NEAR + dt * (float)s;

    float vx = (ox + t*dx + 1.0f) * 80.0f;
    float vy = (oy + t*dy + 1.0f) * 80.0f;
    float vz = (oz + t*dz + 1.0f) * 80.0f;
    vx = fminf(fmaxf(vx, 0.0f), 159.0f);
    vy = fminf(fmaxf(vy, 0.0f), 159.0f);
    vz = fminf(fmaxf(vz, 0.0f), 159.0f);

    const float fx = floorf(vx), fy = floorf(vy), fz = floorf(vz);
    const int x0 = (int)fx, y0 = (int)fy, z0 = (int)fz;
    const int x1 = min(x0 + 1, GRES - 1);
    const int y1 = min(y0 + 1, GRES - 1);
    const int z1 = min(z0 + 1, GRES - 1);
    const float ddx = vx - fx, ddy = vy - fy, ddz = vz - fz;
    const float wx0 = 1.0f - ddx, wx1 = ddx;
    const int   xd  = x1 - x0;

    // ---- Phase 1: density interp + alpha ----
    float dens;
    {
        const int  rz0 = z0 * GRES, rz1 = z1 * GRES;
        const int  i00 = (rz0 + y0) * GRES + x0;
        const int  i01 = (rz0 + y1) * GRES + x0;
        const int  i10 = (rz1 + y0) * GRES + x0;
        const int  i11 = (rz1 + y1) * GRES + x0;
        const float wz0 = 1.0f - ddz, wz1 = ddz;
        const float wy0 = 1.0f - ddy, wy1 = ddy;

        const float d000 = __ldg(density + i00),  d001 = __ldg(density + i00 + xd);
        const float d010 = __ldg(density + i01),  d011 = __ldg(density + i01 + xd);
        const float d100 = __ldg(density + i10),  d101 = __ldg(density + i10 + xd);
        const float d110 = __ldg(density + i11),  d111 = __ldg(density + i11 + xd);

        dens = wz0 * (wy0 * (wx0*d000 + wx1*d001) + wy1 * (wx0*d010 + wx1*d011))
             + wz1 * (wy0 * (wx0*d100 + wx1*d101) + wy1 * (wx0*d110 + wx1*d111));
    }

    const float dist  = ((s == NSAMP - 1) ? 1e10f : dt) * dnorm;
    const float alpha = 1.0f - __expf(-fmaxf(dens, 0.0f) * dist);

    // warp-local exclusive cumprod of (1 - alpha + 1e-10)
    float incl = 1.0f - alpha + 1e-10f;
    #pragma unroll
    for (int o = 1; o < 32; o <<= 1) {
        const float pv = __shfl_up_sync(FULLMASK, incl, o);
        if (lane >= o) incl *= pv;
    }
    float excl = __shfl_up_sync(FULLMASK, incl, 1);
    if (lane == 0) excl = 1.0f;
    const float warpProd = __shfl_sync(FULLMASK, incl, 31);

    if (lane == 0) sProd[wir] = warpProd;
    __syncthreads();

    float P = 1.0f;
    #pragma unroll
    for (int j = 0; j < 3; j++) if (j < wir) P *= sProd[j];
    const float w = alpha * excl * P;    // global weight

    // ---- depth/acc (all samples, fixed order) ----
    {
        float dep = w * t, acc = w;
        #pragma unroll
        for (int o = 16; o > 0; o >>= 1) {
            dep += __shfl_xor_sync(FULLMASK, dep, o);
            acc += __shfl_xor_sync(FULLMASK, acc, o);
        }
        if (lane == 0) { sDep[wir] = dep; sAcc[wir] = acc; }
    }

    // ---- Dedup identical-coord runs ----
    const float pvx = __shfl_up_sync(FULLMASK, vx, 1);
    const float pvy = __shfl_up_sync(FULLMASK, vy, 1);
    const float pvz = __shfl_up_sync(FULLMASK, vz, 1);
    const bool start = (lane == 0) || (vx != pvx) || (vy != pvy) || (vz != pvz);

    const unsigned sb      = __ballot_sync(FULLMASK, start);
    const unsigned mask_le = 0xffffffffu >> (31 - lane);
    const int      segid   = __popc(sb & mask_le);

    float wrun = w;
    #pragma unroll
    for (int o = 1; o < 32; o <<= 1) {
        const float wn = __shfl_down_sync(FULLMASK, wrun, o);
        const int   sn = __shfl_down_sync(FULLMASK, segid, o);
        if (lane + o < 32 && sn == segid) wrun += wn;
    }

    // ---- Compact ----
    const bool push = start && (wrun != 0.0f);
    const unsigned pb = __ballot_sync(FULLMASK, push);
    if (lane == 0) sWarpCnt[wir] = __popc(pb);
    __syncthreads();

    int base = 0, cnt = 0;
    #pragma unroll
    for (int j = 0; j < 4; j++) {
        if (j < wir) base += sWarpCnt[j];
        cnt += sWarpCnt[j];
    }
    if (push) {
        const unsigned mask_lt = mask_le ^ (1u << lane);
        const int pos = base + __popc(pb & mask_lt);
        sSid[pos] = (unsigned char)s;
        sW[pos]   = wrun;
    }
    __syncthreads();

    // ---- Worker phase: 2 lanes per item (parity = z-plane) ----
    float rgb0 = 0.f, rgb1 = 0.f, rgb2 = 0.f;
    const int parity = threadIdx.x & 1;
    const int passes = (cnt + 63) >> 6;

    for (int p = 0; p < passes; p++) {
        const int it    = (p << 6) + (threadIdx.x >> 1);
        const bool valid = (it < cnt);

        float c0 = 0.f, c1 = 0.f, c2 = 0.f;
        float ww = 0.f, wzp = 0.f;

        if (valid) {
            const int   ss = sSid[it];
            ww = sW[it];
            const float tt = T_NEAR + dt * (float)ss;

            float ux = (ox + tt*dx + 1.0f) * 80.0f;
            float uy = (oy + tt*dy + 1.0f) * 80.0f;
            float uz = (oz + tt*dz + 1.0f) * 80.0f;
            ux = fminf(fmaxf(ux, 0.0f), 159.0f);
            uy = fminf(fmaxf(uy, 0.0f), 159.0f);
            uz = fminf(fmaxf(uz, 0.0f), 159.0f);

            const float gx = floorf(ux), gy = floorf(uy), gz = floorf(uz);
            const int a0  = (int)gx, b0i = (int)gy, c0i = (int)gz;
            const int a1  = min(a0  + 1, GRES - 1);
            const int b1i = min(b0i + 1, GRES - 1);
            const int c1i = min(c0i + 1, GRES - 1);
            const float ex = ux - gx, ey = uy - gy, ez = uz - gz;
            const float qx0 = 1.0f - ex, qx1 = ex;
            const int   ad  = a1 - a0;

            // this lane's z-plane
            const int   zi = parity ? c1i : c0i;
            wzp = parity ? ez : (1.0f - ez);
            const int rowz = zi * GRES;

            #pragma unroll 1
            for (int cy = 0; cy < 2; cy++) {
                const int   yi  = cy ? b1i : b0i;
                const float wy  = cy ? ey : (1.0f - ey);
                const int idx0 = (rowz + yi) * GRES + a0;
                sh_row_accum(sh4, idx0,      b, wy * qx0, c0, c1, c2);
                sh_row_accum(sh4, idx0 + ad, b, wy * qx1, c0, c1, c2);
            }
            c0 *= wzp; c1 *= wzp; c2 *= wzp;
        }

        // combine pair (lanes reconverged here; both lanes of a pair share validity)
        c0 += __shfl_xor_sync(FULLMASK, c0, 1);
        c1 += __shfl_xor_sync(FULLMASK, c1, 1);
        c2 += __shfl_xor_sync(FULLMASK, c2, 1);

        if (valid && parity == 0) {
            const float col0 = __fdividef(1.0f, 1.0f + __expf(-c0));
            const float col1 = __fdividef(1.0f, 1.0f + __expf(-c1));
            const float col2 = __fdividef(1.0f, 1.0f + __expf(-c2));
            rgb0 = fmaf(ww, col0, rgb0);
            rgb1 = fmaf(ww, col1, rgb1);
            rgb2 = fmaf(ww, col2, rgb2);
        }
    }

    // fixed-order warp reduction of rgb partials
    #pragma unroll
    for (int o = 16; o > 0; o >>= 1) {
        rgb0 += __shfl_xor_sync(FULLMASK, rgb0, o);
        rgb1 += __shfl_xor_sync(FULLMASK, rgb1, o);
        rgb2 += __shfl_xor_sync(FULLMASK, rgb2, o);
    }
    if (lane == 0) {
        sWacc[wir][0] = rgb0;
        sWacc[wir][1] = rgb1;
        sWacc[wir][2] = rgb2;
    }
    __syncthreads();

    if (threadIdx.x == 0) {
        float o0 = 0.f, o1 = 0.f, o2 = 0.f, od = 0.f, oa = 0.f;
        #pragma unroll
        for (int j = 0; j < 4; j++) {
            o0 += sWacc[j][0];
            o1 += sWacc[j][1];
            o2 += sWacc[j][2];
            od += sDep[j];
            oa += sAcc[j];
        }
        out[r*3 + 0] = o0;
        out[r*3 + 1] = o1;
        out[r*3 + 2] = o2;
        out[R*3 + r] = od;
        out[R*4 + r] = oa;
    }
}

extern "C" void kernel_launch(void* const* d_in, const int* in_sizes, int n_in,
                              void* d_out, int out_size)
{
    const float* ro      = (const float*)d_in[0];
    const float* rd      = (const float*)d_in[1];
    const float* density = (const float*)d_in[2];
    const float* sh      = (const float*)d_in[3];
    float* out           = (float*)d_out;

    const int R = in_sizes[0] / 3;      // 4096 rays, 1 ray per 128-thread block
    plenoxel_fwd_kernel<<<R, 128>>>(ro, rd, density, sh, out, R);
}

// round 10
// speedup vs baseline: 1.1542x; 1.0069x over previous
#include <cuda_runtime.h>

// Plenoxel forward: R=4096 rays, S=128 samples/ray, 160^3 grid.
// Block = 128 threads = 1 ray (1 sample/lane in phase 1).
// Phase 1: density interp, alpha, GLOBAL transmittance weight w per sample.
// Dedup:   runs of identical clamped coords fold weights into one rep.
// Compact: surviving (coords,w) -> smem (coords stashed, NOT recomputed);
//          worker phase assigns 2 lanes per item (parity = z-plane).
// __launch_bounds__(128,8): cap 64 regs -> 8 blocks/SM (occupancy-limited kernel).

#define GRES        160
#define NSAMP       128
#define T_NEAR      0.1f
#define T_FAR       10.0f
#define FULLMASK    0xffffffffu

// Batched 8-chunk window (max MLP) + shifted-basis (23 SELs).
__device__ __forceinline__ void sh_row_accum(const float4* __restrict__ sh4, int idx,
                                             const float (&b)[9], float wgt,
                                             float& c0, float& c1, float& c2)
{
    const int F    = idx * 27;
    const int base = F >> 2;
    const int O    = F & 3;
    const bool s2  = (O & 2) != 0;
    const bool s1  = (O & 1) != 0;

    float v[32];
    #pragma unroll
    for (int i = 0; i < 7; i++) {
        const float4 q = __ldg(sh4 + base + i);
        v[4*i+0] = q.x; v[4*i+1] = q.y; v[4*i+2] = q.z; v[4*i+3] = q.w;
    }
    {   // 8th chunk only needed (and only in-bounds-required) when O>=2
        float4 q = make_float4(0.f, 0.f, 0.f, 0.f);
        if (s2) q = __ldg(sh4 + base + 7);
        v[28] = q.x; v[29] = q.y; v[30] = q.z; v[31] = q.w;
    }

    float t[12];
    t[0]  = s2 ? 0.f  : b[0];
    t[1]  = s2 ? 0.f  : b[1];
    #pragma unroll
    for (int k = 2; k <= 8; k++) t[k] = s2 ? b[k-2] : b[k];
    t[9]  = s2 ? b[7] : 0.f;
    t[10] = s2 ? b[8] : 0.f;
    t[11] = 0.f;

    float bs[12];
    bs[0] = s1 ? 0.f : t[0];
    #pragma unroll
    for (int k = 1; k < 12; k++) bs[k] = s1 ? t[k-1] : t[k];

    float d0 = 0.f, d1 = 0.f, d2 = 0.f;
    #pragma unroll
    for (int k = 0; k < 12; k++) {
        const float bk = bs[k];
        d0 = fmaf(v[k],      bk, d0);
        d1 = fmaf(v[9 + k],  bk, d1);
        d2 = fmaf(v[18 + k], bk, d2);
    }
    c0 = fmaf(wgt, d0, c0);
    c1 = fmaf(wgt, d1, c1);
    c2 = fmaf(wgt, d2, c2);
}

__global__ __launch_bounds__(128, 8) void plenoxel_fwd_kernel(
    const float* __restrict__ ro,
    const float* __restrict__ rd,
    const float* __restrict__ density,
    const float* __restrict__ sh,
    float* __restrict__ out,
    int R)
{
    const float4* __restrict__ sh4 = (const float4*)sh;

    const int wir  = threadIdx.x >> 5;      // warp 0..3
    const int lane = threadIdx.x & 31;
    const int r    = blockIdx.x;             // one ray per block
    const int s    = threadIdx.x;             // sample 0..127

    __shared__ float sProd[4];
    __shared__ float sDep[4], sAcc[4];
    __shared__ float sWacc[4][3];
    __shared__ float sW[128];
    __shared__ float sVx[128], sVy[128], sVz[128];
    __shared__ int   sWarpCnt[4];

    const float ox = ro[r*3+0], oy = ro[r*3+1], oz = ro[r*3+2];
    const float dx = rd[r*3+0], dy = rd[r*3+1], dz = rd[r*3+2];

    const float dnorm = sqrtf(dx*dx + dy*dy + dz*dz);
    const float inv   = 1.0f / (dnorm + 1e-8f);
    const float nx = dx*inv, ny = dy*inv, nz = dz*inv;

    float b[9];
    b[0] =  0.28209479177387814f;
    b[1] = -0.48860251190291987f * ny;
    b[2] =  0.48860251190291987f * nz;
    b[3] = -0.48860251190291987f * nx;
    b[4] =  1.0925484305920792f  * nx * ny;
    b[5] = -1.0925484305920792f  * ny * nz;
    b[6] =  0.31539156525252005f * (2.0f*nz*nz - nx*nx - ny*ny);
    b[7] = -1.0925484305920792f  * nx * nz;
    b[8] =  0.5462742152960396f  * (nx*nx - ny*ny);

    const float dt = (T_FAR - T_NEAR) / (float)(NSAMP - 1);
    const float t  = T_NEAR + dt * (float)s;

    float vx = (ox + t*dx + 1.0f) * 80.0f;
    float vy = (oy + t*dy + 1.0f) * 80.0f;
    float vz = (oz + t*dz + 1.0f) * 80.0f;
    vx = fminf(fmaxf(vx, 0.0f), 159.0f);
    vy = fminf(fmaxf(vy, 0.0f), 159.0f);
    vz = fminf(fmaxf(vz, 0.0f), 159.0f);

    const float fx = floorf(vx), fy = floorf(vy), fz = floorf(vz);
    const int x0 = (int)fx, y0 = (int)fy, z0 = (int)fz;
    const int x1 = min(x0 + 1, GRES - 1);
    const int y1 = min(y0 + 1, GRES - 1);
    const int z1 = min(z0 + 1, GRES - 1);
    const float ddx = vx - fx, ddy = vy - fy, ddz = vz - fz;
    const float wx0 = 1.0f - ddx, wx1 = ddx;
    const int   xd  = x1 - x0;

    // ---- Phase 1: density interp + alpha ----
    float dens;
    {
        const int  rz0 = z0 * GRES, rz1 = z1 * GRES;
        const int  i00 = (rz0 + y0) * GRES + x0;
        const int  i01 = (rz0 + y1) * GRES + x0;
        const int  i10 = (rz1 + y0) * GRES + x0;
        const int  i11 = (rz1 + y1) * GRES + x0;
        const float wz0 = 1.0f - ddz, wz1 = ddz;
        const float wy0 = 1.0f - ddy, wy1 = ddy;

        const float d000 = __ldg(density + i00),  d001 = __ldg(density + i00 + xd);
        const float d010 = __ldg(density + i01),  d011 = __ldg(density + i01 + xd);
        const float d100 = __ldg(density + i10),  d101 = __ldg(density + i10 + xd);
        const float d110 = __ldg(density + i11),  d111 = __ldg(density + i11 + xd);

        dens = wz0 * (wy0 * (wx0*d000 + wx1*d001) + wy1 * (wx0*d010 + wx1*d011))
             + wz1 * (wy0 * (wx0*d100 + wx1*d101) + wy1 * (wx0*d110 + wx1*d111));
    }

    const float dist  = ((s == NSAMP - 1) ? 1e10f : dt) * dnorm;
    const float alpha = 1.0f - __expf(-fmaxf(dens, 0.0f) * dist);

    // warp-local exclusive cumprod of (1 - alpha + 1e-10)
    float incl = 1.0f - alpha + 1e-10f;
    #pragma unroll
    for (int o = 1; o < 32; o <<= 1) {
        const float pv = __shfl_up_sync(FULLMASK, incl, o);
        if (lane >= o) incl *= pv;
    }
    float excl = __shfl_up_sync(FULLMASK, incl, 1);
    if (lane == 0) excl = 1.0f;
    const float warpProd = __shfl_sync(FULLMASK, incl, 31);

    if (lane == 0) sProd[wir] = warpProd;
    __syncthreads();

    float P = 1.0f;
    #pragma unroll
    for (int j = 0; j < 3; j++) if (j < wir) P *= sProd[j];
    const float w = alpha * excl * P;    // global weight

    // ---- depth/acc (all samples, fixed order) ----
    {
        float dep = w * t, acc = w;
        #pragma unroll
        for (int o = 16; o > 0; o >>= 1) {
            dep += __shfl_xor_sync(FULLMASK, dep, o);
            acc += __shfl_xor_sync(FULLMASK, acc, o);
        }
        if (lane == 0) { sDep[wir] = dep; sAcc[wir] = acc; }
    }

    // ---- Dedup identical-coord runs ----
    const float pvx = __shfl_up_sync(FULLMASK, vx, 1);
    const float pvy = __shfl_up_sync(FULLMASK, vy, 1);
    const float pvz = __shfl_up_sync(FULLMASK, vz, 1);
    const bool start = (lane == 0) || (vx != pvx) || (vy != pvy) || (vz != pvz);

    const unsigned sb      = __ballot_sync(FULLMASK, start);
    const unsigned mask_le = 0xffffffffu >> (31 - lane);
    const int      segid   = __popc(sb & mask_le);

    float wrun = w;
    #pragma unroll
    for (int o = 1; o < 32; o <<= 1) {
        const float wn = __shfl_down_sync(FULLMASK, wrun, o);
        const int   sn = __shfl_down_sync(FULLMASK, segid, o);
        if (lane + o < 32 && sn == segid) wrun += wn;
    }

    // ---- Compact: stash coords + folded weight ----
    const bool push = start && (wrun != 0.0f);
    const unsigned pb = __ballot_sync(FULLMASK, push);
    if (lane == 0) sWarpCnt[wir] = __popc(pb);
    __syncthreads();

    int base = 0, cnt = 0;
    #pragma unroll
    for (int j = 0; j < 4; j++) {
        if (j < wir) base += sWarpCnt[j];
        cnt += sWarpCnt[j];
    }
    if (push) {
        const unsigned mask_lt = mask_le ^ (1u << lane);
        const int pos = base + __popc(pb & mask_lt);
        sW[pos]  = wrun;
        sVx[pos] = vx;
        sVy[pos] = vy;
        sVz[pos] = vz;
    }
    __syncthreads();

    // ---- Worker phase: 2 lanes per item (parity = z-plane), coords from smem ----
    float rgb0 = 0.f, rgb1 = 0.f, rgb2 = 0.f;
    const int parity = threadIdx.x & 1;
    const int passes = (cnt + 63) >> 6;

    for (int p = 0; p < passes; p++) {
        const int it    = (p << 6) + (threadIdx.x >> 1);
        const bool valid = (it < cnt);

        float c0 = 0.f, c1 = 0.f, c2 = 0.f;
        float ww = 0.f;

        if (valid) {
            const float ux = sVx[it];
            const float uy = sVy[it];
            const float uz = sVz[it];
            ww = sW[it];

            const float gx = floorf(ux), gy = floorf(uy), gz = floorf(uz);
            const int a0  = (int)gx, b0i = (int)gy, c0i = (int)gz;
            const int a1  = min(a0  + 1, GRES - 1);
            const int b1i = min(b0i + 1, GRES - 1);
            const int c1i = min(c0i + 1, GRES - 1);
            const float ex = ux - gx, ey = uy - gy, ez = uz - gz;
            const float qx0 = 1.0f - ex, qx1 = ex;
            const int   ad  = a1 - a0;

            // this lane's z-plane
            const int   zi  = parity ? c1i : c0i;
            const float wzp = parity ? ez : (1.0f - ez);
            const int rowz  = zi * GRES;

            #pragma unroll 1
            for (int cy = 0; cy < 2; cy++) {
                const int   yi = cy ? b1i : b0i;
                const float wy = cy ? ey : (1.0f - ey);
                const int idx0 = (rowz + yi) * GRES + a0;
                sh_row_accum(sh4, idx0,      b, wy * qx0, c0, c1, c2);
                sh_row_accum(sh4, idx0 + ad, b, wy * qx1, c0, c1, c2);
            }
            c0 *= wzp; c1 *= wzp; c2 *= wzp;
        }

        // combine pair (lanes reconverged; both lanes of a pair share validity)
        c0 += __shfl_xor_sync(FULLMASK, c0, 1);
        c1 += __shfl_xor_sync(FULLMASK, c1, 1);
        c2 += __shfl_xor_sync(FULLMASK, c2, 1);

        if (valid && parity == 0) {
            const float col0 = __fdividef(1.0f, 1.0f + __expf(-c0));
            const float col1 = __fdividef(1.0f, 1.0f + __expf(-c1));
            const float col2 = __fdividef(1.0f, 1.0f + __expf(-c2));
            rgb0 = fmaf(ww, col0, rgb0);
            rgb1 = fmaf(ww, col1, rgb1);
            rgb2 = fmaf(ww, col2, rgb2);
        }
    }

    // fixed-order warp reduction of rgb partials
    #pragma unroll
    for (int o = 16; o > 0; o >>= 1) {
        rgb0 += __shfl_xor_sync(FULLMASK, rgb0, o);
        rgb1 += __shfl_xor_sync(FULLMASK, rgb1, o);
        rgb2 += __shfl_xor_sync(FULLMASK, rgb2, o);
    }
    if (lane == 0) {
        sWacc[wir][0] = rgb0;
        sWacc[wir][1] = rgb1;
        sWacc[wir][2] = rgb2;
    }
    __syncthreads();

    if (threadIdx.x == 0) {
        float o0 = 0.f, o1 = 0.f, o2 = 0.f, od = 0.f, oa = 0.f;
        #pragma unroll
        for (int j = 0; j < 4; j++) {
            o0 += sWacc[j][0];
            o1 += sWacc[j][1];
            o2 += sWacc[j][2];
            od += sDep[j];
            oa += sAcc[j];
        }
        out[r*3 + 0] = o0;
        out[r*3 + 1] = o1;
        out[r*3 + 2] = o2;
        out[R*3 + r] = od;
        out[R*4 + r] = oa;
    }
}

extern "C" void kernel_launch(void* const* d_in, const int* in_sizes, int n_in,
                              void* d_out, int out_size)
{
    const float* ro      = (const float*)d_in[0];
    const float* rd      = (const float*)d_in[1];
    const float* density = (const float*)d_in[2];
    const float* sh      = (const float*)d_in[3];
    float* out           = (float*)d_out;

    const int R = in_sizes[0] / 3;      // 4096 rays, 1 ray per 128-thread block
    plenoxel_fwd_kernel<<<R, 128>>>(ro, rd, density, sh, out, R);
}